// round 17
// baseline (speedup 1.0000x reference)
#include <cuda_runtime.h>
#include <cstdint>

#define BATCH 64
#define NSTEPS 2000
#define TAPS 64
#define NTHREADS 128
#define CHUNK 16
#define NCHUNK (NSTEPS / CHUNK)   // 125
#define SYM_CHUNKS 6              // symmetrize every 96 steps

using ull = unsigned long long;

__device__ __forceinline__ void cp16(uint32_t dst_smem, const void* src_gmem) {
    asm volatile("cp.async.cg.shared.global [%0], [%1], 16;\n"
                 :: "r"(dst_smem), "l"(src_gmem));
}
__device__ __forceinline__ void cp_commit() {
    asm volatile("cp.async.commit_group;\n");
}
template <int N>
__device__ __forceinline__ void cp_wait() {
    asm volatile("cp.async.wait_group %0;\n" :: "n"(N));
}

// ---- packed f32x2 ops (Blackwell sm_103a) ----
__device__ __forceinline__ ull ffma2(ull a, ull b, ull c) {
    ull d; asm("fma.rn.f32x2 %0, %1, %2, %3;" : "=l"(d) : "l"(a), "l"(b), "l"(c));
    return d;
}
__device__ __forceinline__ ull fadd2(ull a, ull b) {
    ull d; asm("add.rn.f32x2 %0, %1, %2;" : "=l"(d) : "l"(a), "l"(b));
    return d;
}
__device__ __forceinline__ ull pack2(float x) {
    ull d; uint32_t t = __float_as_uint(x);
    asm("mov.b64 %0, {%1, %2};" : "=l"(d) : "r"(t), "r"(t));
    return d;
}
__device__ __forceinline__ ull pack2two(float a, float b) {
    ull d;
    asm("mov.b64 %0, {%1, %2};" : "=l"(d)
        : "r"(__float_as_uint(a)), "r"(__float_as_uint(b)));
    return d;
}
__device__ __forceinline__ void unpack2(ull v, float& a, float& b) {
    uint32_t lo, hi;
    asm("mov.b64 {%0, %1}, %2;" : "=r"(lo), "=r"(hi) : "l"(v));
    a = __uint_as_float(lo); b = __uint_as_float(hi);
}
__device__ __forceinline__ float hadd2(ull v) {
    float a, b; unpack2(v, a, b); return a + b;
}

__global__ void __launch_bounds__(NTHREADS, 1)
rls_kernel(const float* __restrict__ x_seq,
           const float* __restrict__ d_seq,
           const float* __restrict__ lambdas,
           float* __restrict__ y_out,
           float* __restrict__ w_out)
{
    const int b    = blockIdx.x;
    const int tid  = threadIdx.x;
    const int i    = tid >> 1;   // row 0..63
    const int c    = tid & 1;    // column-half 0/1 (== lane parity)
    const int lane = tid & 31;
    const int warp = tid >> 5;

    __shared__ __align__(16) float xc[4][CHUNK][TAPS];   // rotating chunk bufs
    __shared__ __align__(16) float dc[4][CHUNK];
    __shared__ __align__(16) float lc[4][CHUNK];
    __shared__ __align__(16) float ub[2][4][TAPS];       // u1..u4, ping-pong
    __shared__ __align__(32) float4 redE[2][4][2];       // even-lane sums per warp
    __shared__ __align__(32) float4 redO[2][4][2];       // odd-lane sums per warp
    __shared__ float tile[TAPS][TAPS + 1];

    // Q row-half packed: 16 x f32x2 (cols [32c,32c+32)).  P = Q / rho.
    ull Q2[16];
#pragma unroll
    for (int k = 0; k < 16; k++) {
        const int j0 = c * 32 + 2 * k;
        Q2[k] = pack2two(i == j0 ? 1.0f : 0.0f, i == j0 + 1 ? 1.0f : 0.0f);
    }
    float wi  = 0.0f;    // w_i row scalar (identical on both c threads)
    float rho = 1.0f;    // rho = prod(lambda) = 1/sigma

    const float* xgb = x_seq + (size_t)b * NSTEPS * TAPS;
    const float* dgb = d_seq + (size_t)b * NSTEPS;
    float* yo = y_out + (size_t)b * NSTEPS;

    const uint32_t xc_s = (uint32_t)__cvta_generic_to_shared(&xc[0][0][0]);
    const uint32_t dc_s = (uint32_t)__cvta_generic_to_shared(&dc[0][0]);
    const uint32_t lc_s = (uint32_t)__cvta_generic_to_shared(&lc[0][0]);

    auto issue_chunk = [&](int ck, int cb) {
#pragma unroll
        for (int j = 0; j < 2; j++)
            cp16(xc_s + (uint32_t)(cb * (CHUNK * TAPS) + j * 512) * 4 + tid * 16,
                 xgb + (size_t)ck * CHUNK * TAPS + j * 512 + tid * 4);
        if (tid < 4)
            cp16(dc_s + (uint32_t)(cb * CHUNK) * 4 + tid * 16,
                 dgb + ck * CHUNK + tid * 4);
        else if (tid < 8)
            cp16(lc_s + (uint32_t)(cb * CHUNK) * 4 + (tid - 4) * 16,
                 lambdas + ck * CHUNK + (tid - 4) * 4);
        cp_commit();
    };

    issue_chunk(0, 0);
    issue_chunk(1, 1);
    cp_wait<1>();
    __syncthreads();

    for (int ck = 0; ck < NCHUNK; ck++) {
        if (ck + 2 < NCHUNK) { issue_chunk(ck + 2, (ck + 2) & 3); cp_wait<1>(); }
        else                 { cp_wait<0>(); }
        __syncthreads();
        const int cb = ck & 3;

        // 4 rank-4 blocks per chunk (steps 4m .. 4m+3)
#pragma unroll
        for (int blk = 0; blk < CHUNK / 4; blk++) {
            const int s  = 4 * blk;
            const int t  = ck * CHUNK + s;
            const int pb = blk & 1;

            const float* xp = &xc[cb][s][0];   // rows s..s+3 contiguous

            // ===== hoisted: x row scalars + W-trees (independent of matvec) ====
            const float x1i = xp[i];
            const float x2i = xp[TAPS + i];
            const float x3i = xp[2 * TAPS + i];
            const float x4i = xp[3 * TAPS + i];
            float T6 = (c == 0) ? wi * x1i : wi * x2i;   // W1 | W2
            float T7 = (c == 0) ? wi * x3i : wi * x4i;   // W3 | W4
#pragma unroll
            for (int off = 16; off >= 2; off >>= 1) {
                T6 += __shfl_xor_sync(0xffffffffu, T6, off);
                T7 += __shfl_xor_sync(0xffffffffu, T7, off);
            }

            // ===== Phase A: u_j = Q x_j, j = 1..4 =====
            ull a1 = 0ull, b1 = 0ull, a2 = 0ull, b2 = 0ull;
            ull a3 = 0ull, b3 = 0ull, a4 = 0ull, b4 = 0ull;
#pragma unroll
            for (int k = 0; k < 8; k++) {
                const ulonglong2 v1 = *(const ulonglong2*)(xp + 0 * TAPS + c * 32 + 4 * k);
                const ulonglong2 v2 = *(const ulonglong2*)(xp + 1 * TAPS + c * 32 + 4 * k);
                const ulonglong2 v3 = *(const ulonglong2*)(xp + 2 * TAPS + c * 32 + 4 * k);
                const ulonglong2 v4 = *(const ulonglong2*)(xp + 3 * TAPS + c * 32 + 4 * k);
                a1 = ffma2(Q2[2 * k], v1.x, a1); b1 = ffma2(Q2[2 * k + 1], v1.y, b1);
                a2 = ffma2(Q2[2 * k], v2.x, a2); b2 = ffma2(Q2[2 * k + 1], v2.y, b2);
                a3 = ffma2(Q2[2 * k], v3.x, a3); b3 = ffma2(Q2[2 * k + 1], v3.y, b3);
                a4 = ffma2(Q2[2 * k], v4.x, a4); b4 = ffma2(Q2[2 * k + 1], v4.y, b4);
            }
            float u1i = hadd2(fadd2(a1, b1));
            float u2i = hadd2(fadd2(a2, b2));
            float u3i = hadd2(fadd2(a3, b3));
            float u4i = hadd2(fadd2(a4, b4));
            u1i += __shfl_xor_sync(0xffffffffu, u1i, 1);
            u2i += __shfl_xor_sync(0xffffffffu, u2i, 1);
            u3i += __shfl_xor_sync(0xffffffffu, u3i, 1);
            u4i += __shfl_xor_sync(0xffffffffu, u4i, 1);
            if (c == 0) {
                ub[pb][0][i] = u1i; ub[pb][1][i] = u2i;
                ub[pb][2][i] = u3i; ub[pb][3][i] = u4i;
            }

            // ===== remaining 10 Gram scalars via 5 parity trees =====
            float T1 = (c == 0) ? u1i * x1i : u1i * x2i;   // G11 | G12
            float T2 = (c == 0) ? u1i * x3i : u1i * x4i;   // G13 | G14
            float T3 = (c == 0) ? u2i * x2i : u2i * x3i;   // G22 | G23
            float T4 = (c == 0) ? u2i * x4i : u3i * x3i;   // G24 | G33
            float T5 = (c == 0) ? u3i * x4i : u4i * x4i;   // G34 | G44
#pragma unroll
            for (int off = 16; off >= 2; off >>= 1) {
                T1 += __shfl_xor_sync(0xffffffffu, T1, off);
                T2 += __shfl_xor_sync(0xffffffffu, T2, off);
                T3 += __shfl_xor_sync(0xffffffffu, T3, off);
                T4 += __shfl_xor_sync(0xffffffffu, T4, off);
                T5 += __shfl_xor_sync(0xffffffffu, T5, off);
            }
            if (lane == 0) {
                redE[pb][warp][0] = make_float4(T1, T2, T3, T4);
                redE[pb][warp][1] = make_float4(T5, T6, T7, 0.0f);
            }
            if (lane == 1) {
                redO[pb][warp][0] = make_float4(T1, T2, T3, T4);
                redO[pb][warp][1] = make_float4(T5, T6, T7, 0.0f);
            }

            const float d1 = dc[cb][s],     d2 = dc[cb][s + 1];
            const float d3 = dc[cb][s + 2], d4 = dc[cb][s + 3];
            const float l1 = fminf(fmaxf(lc[cb][s],     1e-4f), 0.9999f);
            const float l2 = fminf(fmaxf(lc[cb][s + 1], 1e-4f), 0.9999f);
            const float l3 = fminf(fmaxf(lc[cb][s + 2], 1e-4f), 0.9999f);
            const float l4 = fminf(fmaxf(lc[cb][s + 3], 1e-4f), 0.9999f);

            __syncthreads();   // the ONE barrier per 4 steps

            // ===== early u1/u2 loads (LDS latency overlaps scalar phase) =====
            ulonglong2 eu1[8], eu2[8];
#pragma unroll
            for (int k = 0; k < 8; k++) {
                eu1[k] = *(const ulonglong2*)(&ub[pb][0][c * 32 + 4 * k]);
                eu2[k] = *(const ulonglong2*)(&ub[pb][1][c * 32 + 4 * k]);
            }

            // ===== Phase B: packed combine (f32x2 adds) =====
            const ulonglong2* rE = (const ulonglong2*)&redE[pb][0][0];
            const ulonglong2* rO = (const ulonglong2*)&redO[pb][0][0];
            const ulonglong2 e0 = rE[0], e1v = rE[2], e2v = rE[4], e3v = rE[6];
            const ulonglong2 f0 = rE[1], f1v = rE[3], f2v = rE[5], f3v = rE[7];
            const ulonglong2 o0 = rO[0], o1v = rO[2], o2v = rO[4], o3v = rO[6];
            const ulonglong2 p0 = rO[1], p1v = rO[3], p2v = rO[5], p3v = rO[7];
            const ull E0 = fadd2(fadd2(e0.x, e1v.x), fadd2(e2v.x, e3v.x));
            const ull E1 = fadd2(fadd2(e0.y, e1v.y), fadd2(e2v.y, e3v.y));
            const ull E2 = fadd2(fadd2(f0.x, f1v.x), fadd2(f2v.x, f3v.x));
            const ull E3 = fadd2(fadd2(f0.y, f1v.y), fadd2(f2v.y, f3v.y));
            const ull O0 = fadd2(fadd2(o0.x, o1v.x), fadd2(o2v.x, o3v.x));
            const ull O1 = fadd2(fadd2(o0.y, o1v.y), fadd2(o2v.y, o3v.y));
            const ull O2 = fadd2(fadd2(p0.x, p1v.x), fadd2(p2v.x, p3v.x));
            const ull O3 = fadd2(fadd2(p0.y, p1v.y), fadd2(p2v.y, p3v.y));
            float G11, G13; unpack2(E0, G11, G13);
            float G22, G24; unpack2(E1, G22, G24);
            float G34, W1;  unpack2(E2, G34, W1);
            float W3, pe;   unpack2(E3, W3, pe);
            float G12, G14; unpack2(O0, G12, G14);
            float G23, G33; unpack2(O1, G23, G33);
            float G44, W2;  unpack2(O2, G44, W2);
            float W4, po;   unpack2(O3, W4, po);

            // ===== gains via leading principal minors (parallel, no chain) =====
            const float P1 = rho * l1, P2 = P1 * l2, P3 = P2 * l3, P4 = P3 * l4;
            const float sa = P1 + G11, se = P2 + G22, sh = P3 + G33, sj = P4 + G44;
            const float ra = __fdividef(1.0f, sa);
            const float bp2 = G12 * ra, cp2 = G13 * ra, dp2 = G14 * ra;
            const float ep2 = se  * ra, fp2 = G23 * ra, gp2 = G24 * ra;
            const float hp2 = sh  * ra, ip2 = G34 * ra, jp2 = sj  * ra;
            const float det2p = fmaf(-bp2, bp2, ep2);
            const float det3p = (ep2 * hp2 - fp2 * fp2)
                              - bp2 * (bp2 * hp2 - fp2 * cp2)
                              + cp2 * (bp2 * fp2 - ep2 * cp2);
            const float m1 = fmaf(hp2, jp2, -ip2 * ip2);
            const float m2 = fmaf(fp2, jp2, -gp2 * ip2);
            const float m3 = fmaf(fp2, ip2, -gp2 * hp2);
            const float n1 = fmaf(cp2, jp2, -dp2 * ip2);
            const float n2 = fmaf(cp2, ip2, -dp2 * hp2);
            const float n3 = fmaf(cp2, gp2, -dp2 * fp2);
            const float detL = ep2 * m1 - fp2 * m2 + gp2 * m3;
            const float D2c  = bp2 * m1 - fp2 * n1 + gp2 * n2;
            const float D3c  = bp2 * m2 - ep2 * n1 + gp2 * n3;
            const float D4c  = bp2 * m3 - ep2 * n2 + fp2 * n3;
            const float det4p = detL - bp2 * D2c + cp2 * D3c - dp2 * D4c;
            const float k1 = ra;
            const float k2 = ra * __fdividef(1.0f, det2p);
            const float k3 = ra * det2p * __fdividef(1.0f, det3p);
            const float k4 = ra * det3p * __fdividef(1.0f, det4p);
            rho = P4;

            // ===== off-diag Schur entries (shallow; k's already known) =====
            const float g23 = fmaf(-k1 * G12, G13, G23);
            const float g24 = fmaf(-k1 * G12, G14, G24);
            const float g34 = fmaf(-k2 * g23, g24, fmaf(-k1 * G13, G14, G34));

            // ===== y / e chain (short serial) =====
            const float e1 = d1 - W1;
            const float y2 = fmaf(k1 * e1, G12, W2);
            const float e2 = d2 - y2;
            const float y3 = fmaf(k2 * e2, g23, fmaf(k1 * e1, G13, W3));
            const float e3 = d3 - y3;
            const float y4 = fmaf(k3 * e3, g34,
                             fmaf(k2 * e2, g24, fmaf(k1 * e1, G14, W4)));
            const float e4 = d4 - y4;
            if (tid == 0) { yo[t] = W1; yo[t + 1] = y2; yo[t + 2] = y3; yo[t + 3] = y4; }

            // ===== mu coefficients =====
            const float mu21 = -k1 * G12;
            const float mu31 = fmaf(-k2 * g23, mu21, -k1 * G13);
            const float mu32 = -k2 * g23;
            const float mu41 = fmaf(-k3 * g34, mu31, fmaf(-k2 * g24, mu21, -k1 * G14));
            const float mu42 = fmaf(-k3 * g34, mu32, -k2 * g24);
            const float mu43 = -k3 * g34;

            // ===== C = sum_m k_m mu_m mu_m' (4x4 sym) =====
            const float C11 = k1 + k2 * mu21 * mu21 + k3 * mu31 * mu31 + k4 * mu41 * mu41;
            const float C12 = k2 * mu21 + k3 * mu31 * mu32 + k4 * mu41 * mu42;
            const float C13 = k3 * mu31 + k4 * mu41 * mu43;
            const float C14 = k4 * mu41;
            const float C22 = k2 + k3 * mu32 * mu32 + k4 * mu42 * mu42;
            const float C23 = k3 * mu32 + k4 * mu42 * mu43;
            const float C24 = k4 * mu42;
            const float C33 = k3 + k4 * mu43 * mu43;
            const float C34 = k4 * mu43;
            const float C44 = k4;

            // ===== w row-scalar update =====
            const float k1e1 = k1 * e1, k2e2 = k2 * e2, k3e3 = k3 * e3, k4e4 = k4 * e4;
            const float om1 = k1e1 + k2e2 * mu21 + k3e3 * mu31 + k4e4 * mu41;
            const float om2 = k2e2 + k3e3 * mu32 + k4e4 * mu42;
            const float om3 = k3e3 + k4e4 * mu43;
            const float om4 = k4e4;
            wi = fmaf(om1, u1i, fmaf(om2, u2i, fmaf(om3, u3i, fmaf(om4, u4i, wi))));

            // ===== Q -= U C U': row coeffs r_n = sum_m C_mn u_m,i =====
            const float r1 = C11 * u1i + C12 * u2i + C13 * u3i + C14 * u4i;
            const float r2 = C12 * u1i + C22 * u2i + C23 * u3i + C24 * u4i;
            const float r3 = C13 * u1i + C23 * u2i + C33 * u3i + C34 * u4i;
            const float r4 = C14 * u1i + C24 * u2i + C34 * u3i + C44 * u4i;
            const ull nr1 = pack2(-r1), nr2 = pack2(-r2);
            const ull nr3 = pack2(-r3), nr4 = pack2(-r4);
#pragma unroll
            for (int k = 0; k < 8; k++) {
                const ulonglong2 uu3 = *(const ulonglong2*)(&ub[pb][2][c * 32 + 4 * k]);
                const ulonglong2 uu4 = *(const ulonglong2*)(&ub[pb][3][c * 32 + 4 * k]);
                ull qa = Q2[2 * k], qb = Q2[2 * k + 1];
                qa = ffma2(nr1, eu1[k].x, qa); qb = ffma2(nr1, eu1[k].y, qb);
                qa = ffma2(nr2, eu2[k].x, qa); qb = ffma2(nr2, eu2[k].y, qb);
                qa = ffma2(nr3, uu3.x, qa);    qb = ffma2(nr3, uu3.y, qb);
                qa = ffma2(nr4, uu4.x, qa);    qb = ffma2(nr4, uu4.y, qb);
                Q2[2 * k] = qa; Q2[2 * k + 1] = qb;
            }
        }

        // ---- symmetrize every SYM_CHUNKS chunks (kills undamped antisym mode) ----
        if ((ck % SYM_CHUNKS) == (SYM_CHUNKS - 1)) {
            __syncthreads();
#pragma unroll
            for (int k = 0; k < 16; k++) {
                float f0, f1; unpack2(Q2[k], f0, f1);
                tile[i][c * 32 + 2 * k]     = f0;
                tile[i][c * 32 + 2 * k + 1] = f1;
            }
            __syncthreads();
#pragma unroll
            for (int k = 0; k < 16; k++) {
                float f0, f1; unpack2(Q2[k], f0, f1);
                const float t0 = tile[c * 32 + 2 * k][i];
                const float t1 = tile[c * 32 + 2 * k + 1][i];
                Q2[k] = pack2two(0.5f * (f0 + t0), 0.5f * (f1 + t1));
            }
            __syncthreads();
        }
    }

    // ---- outputs: w_i row scalars ----
    if (c == 0) w_out[(size_t)b * TAPS + i] = wi;
}

extern "C" void kernel_launch(void* const* d_in, const int* in_sizes, int n_in,
                              void* d_out, int out_size)
{
    const float* x_seq   = (const float*)d_in[0];
    const float* d_seq   = (const float*)d_in[1];
    const float* lambdas = (const float*)d_in[2];
    float* y_out = (float*)d_out;                          // [64, 2000]
    float* w_out = (float*)d_out + (size_t)BATCH * NSTEPS; // [64, 64]
    rls_kernel<<<BATCH, NTHREADS>>>(x_seq, d_seq, lambdas, y_out, w_out);
}